// round 1
// baseline (speedup 1.0000x reference)
#include <cuda_runtime.h>
#include <math.h>

// ---------------- problem constants ----------------
#define BSZ   2
#define LSEQ  512
#define DMODEL 1024
#define DINNER 2048
#define DSTATE 64
#define KCONV 4
#define MROWS (BSZ*LSEQ)     // 1024
#define NXP   129            // 2*DSTATE + 1
#define KCH   8              // split-K chunks for x-proj
#define KSZ   (DINNER/KCH)   // 256
#define OUT_ELEMS (MROWS*DMODEL)   // 1048576 floats of `out`

// ---------------- device scratch (no allocations allowed) ----------------
__device__ float g_xz  [MROWS * 2 * DINNER]; // in-proj result [m][4096]
__device__ float g_xs  [MROWS * DINNER];     // conv+silu output
__device__ float g_xpp [KCH * MROWS * NXP];  // x-proj split-K partials
__device__ float g_Bm  [MROWS * DSTATE];
__device__ float g_Cm  [MROWS * DSTATE];
__device__ float g_dtr [MROWS];
__device__ float g_dt  [MROWS * DINNER];
__device__ float g_y   [MROWS * DINNER];

// ---------------- generic fp32 SGEMM, 128x128 tile, BK=8 ----------------
// A row-major [M,K], B row-major [K,N], C row-major [M,N].
// Requires M%128==0, N%128==0, K%8==0.
__global__ __launch_bounds__(256) void sgemm128(
    const float* __restrict__ A, const float* __restrict__ B,
    float* __restrict__ C, int M, int N, int K)
{
    __shared__ float As[8][128];
    __shared__ float Bs[8][128];

    const int tid = threadIdx.x;
    const int tx  = tid & 15;   // 0..15 (col group of 8)
    const int ty  = tid >> 4;   // 0..15 (row group of 8)

    const float* Ab = A + (size_t)blockIdx.y * 128 * K;
    const float* Bb = B + (size_t)blockIdx.x * 128;

    const int a_row  = tid >> 1;         // 0..127
    const int a_col4 = (tid & 1) * 4;    // 0 or 4
    const int b_row  = tid >> 5;         // 0..7
    const int b_col4 = (tid & 31) * 4;   // 0..124

    float acc[8][8];
#pragma unroll
    for (int i = 0; i < 8; i++)
#pragma unroll
        for (int j = 0; j < 8; j++) acc[i][j] = 0.f;

    for (int k0 = 0; k0 < K; k0 += 8) {
        float4 av = *(const float4*)(Ab + (size_t)a_row * K + k0 + a_col4);
        As[a_col4 + 0][a_row] = av.x;
        As[a_col4 + 1][a_row] = av.y;
        As[a_col4 + 2][a_row] = av.z;
        As[a_col4 + 3][a_row] = av.w;
        float4 bv = *(const float4*)(Bb + (size_t)(k0 + b_row) * N + b_col4);
        *(float4*)(&Bs[b_row][b_col4]) = bv;
        __syncthreads();
#pragma unroll
        for (int k = 0; k < 8; k++) {
            float ar[8], br[8];
#pragma unroll
            for (int i = 0; i < 8; i++) ar[i] = As[k][ty * 8 + i];
#pragma unroll
            for (int j = 0; j < 8; j++) br[j] = Bs[k][tx * 8 + j];
#pragma unroll
            for (int i = 0; i < 8; i++)
#pragma unroll
                for (int j = 0; j < 8; j++) acc[i][j] += ar[i] * br[j];
        }
        __syncthreads();
    }

    float* Cb = C + (size_t)(blockIdx.y * 128 + ty * 8) * N + blockIdx.x * 128 + tx * 8;
#pragma unroll
    for (int i = 0; i < 8; i++)
#pragma unroll
        for (int j = 0; j < 8; j++) Cb[(size_t)i * N + j] = acc[i][j];
}

// ---------------- fp32 SGEMM, 64x64 tile, BK=16 (more blocks for small N) ----
// Requires M%64==0, N%64==0, K%16==0.
__global__ __launch_bounds__(256) void sgemm64(
    const float* __restrict__ A, const float* __restrict__ B,
    float* __restrict__ C, int M, int N, int K)
{
    __shared__ float As[16][64];
    __shared__ float Bs[16][64];

    const int tid = threadIdx.x;
    const int tx  = tid & 15;   // col group of 4
    const int ty  = tid >> 4;   // row group of 4

    const float* Ab = A + (size_t)blockIdx.y * 64 * K;
    const float* Bb = B + (size_t)blockIdx.x * 64;

    const int a_row  = tid >> 2;        // 0..63
    const int a_col4 = (tid & 3) * 4;   // 0..12
    const int b_row  = tid >> 4;        // 0..15
    const int b_col4 = (tid & 15) * 4;  // 0..60

    float acc[4][4];
#pragma unroll
    for (int i = 0; i < 4; i++)
#pragma unroll
        for (int j = 0; j < 4; j++) acc[i][j] = 0.f;

    for (int k0 = 0; k0 < K; k0 += 16) {
        float4 av = *(const float4*)(Ab + (size_t)a_row * K + k0 + a_col4);
        As[a_col4 + 0][a_row] = av.x;
        As[a_col4 + 1][a_row] = av.y;
        As[a_col4 + 2][a_row] = av.z;
        As[a_col4 + 3][a_row] = av.w;
        float4 bv = *(const float4*)(Bb + (size_t)(k0 + b_row) * N + b_col4);
        *(float4*)(&Bs[b_row][b_col4]) = bv;
        __syncthreads();
#pragma unroll
        for (int k = 0; k < 16; k++) {
            float ar[4], br[4];
#pragma unroll
            for (int i = 0; i < 4; i++) ar[i] = As[k][ty * 4 + i];
#pragma unroll
            for (int j = 0; j < 4; j++) br[j] = Bs[k][tx * 4 + j];
#pragma unroll
            for (int i = 0; i < 4; i++)
#pragma unroll
                for (int j = 0; j < 4; j++) acc[i][j] += ar[i] * br[j];
        }
        __syncthreads();
    }

    float* Cb = C + (size_t)(blockIdx.y * 64 + ty * 4) * N + blockIdx.x * 64 + tx * 4;
#pragma unroll
    for (int i = 0; i < 4; i++)
#pragma unroll
        for (int j = 0; j < 4; j++) Cb[(size_t)i * N + j] = acc[i][j];
}

// ---------------- depthwise causal conv (K=4) + bias + SiLU ----------------
__global__ void conv_silu_kernel(const float* __restrict__ conv_w,
                                 const float* __restrict__ conv_b)
{
    const int m = blockIdx.x;           // 0..1023
    const int b = m / LSEQ;
    const int l = m % LSEQ;
    for (int c = threadIdx.x; c < DINNER; c += blockDim.x) {
        float s = conv_b[c];
#pragma unroll
        for (int k = 0; k < KCONV; k++) {
            int ls = l - (KCONV - 1) + k;
            if (ls >= 0)
                s += g_xz[(size_t)(b * LSEQ + ls) * (2 * DINNER) + c] * conv_w[c * KCONV + k];
        }
        float sil = s / (1.f + __expf(-s));
        g_xs[(size_t)m * DINNER + c] = sil;
    }
}

// ---------------- x-proj: xp = xs @ x_proj_w  (split-K partials) ------------
// grid (64 m-tiles, KCH k-chunks), block 160 threads (129 active in compute)
__global__ __launch_bounds__(160) void xp_partial_kernel(const float* __restrict__ W)
{
    __shared__ float s[16][KSZ];
    const int m0 = blockIdx.x * 16;
    const int k0 = blockIdx.y * KSZ;
    const int tid = threadIdx.x;

    for (int idx = tid; idx < 16 * KSZ; idx += blockDim.x) {
        int r = idx / KSZ, k = idx % KSZ;
        s[r][k] = g_xs[(size_t)(m0 + r) * DINNER + k0 + k];
    }
    __syncthreads();

    if (tid < NXP) {
        float acc[16];
#pragma unroll
        for (int r = 0; r < 16; r++) acc[r] = 0.f;
        for (int k = 0; k < KSZ; k++) {
            float w = W[(size_t)(k0 + k) * NXP + tid];
#pragma unroll
            for (int r = 0; r < 16; r++) acc[r] += s[r][k] * w;
        }
#pragma unroll
        for (int r = 0; r < 16; r++)
            g_xpp[(size_t)(blockIdx.y * MROWS + m0 + r) * NXP + tid] = acc[r];
    }
}

// reduce split-K partials -> Bm, Cm, dt_raw
__global__ __launch_bounds__(160) void xp_reduce_kernel()
{
    const int m = blockIdx.x;
    const int n = threadIdx.x;
    if (n >= NXP) return;
    float sum = 0.f;
#pragma unroll
    for (int kc = 0; kc < KCH; kc++)
        sum += g_xpp[(size_t)(kc * MROWS + m) * NXP + n];
    if (n < DSTATE)            g_Bm[m * DSTATE + n] = sum;
    else if (n < 2 * DSTATE)   g_Cm[m * DSTATE + (n - DSTATE)] = sum;
    else                       g_dtr[m] = sum;
}

// dt = softplus(dt_raw * dt_w + dt_b)
__global__ void dt_kernel(const float* __restrict__ dt_w,
                          const float* __restrict__ dt_b)
{
    const int m = blockIdx.x;
    const float dr = g_dtr[m];
    for (int c = threadIdx.x; c < DINNER; c += blockDim.x) {
        float v = dr * dt_w[c] + dt_b[c];
        float sp = (v > 20.f) ? v : log1pf(expf(v));
        g_dt[(size_t)m * DINNER + c] = sp;
    }
}

// ---------------- selective scan: one warp per (b, d), 2 states per lane ----
__global__ __launch_bounds__(256) void scan_kernel(
    const float* __restrict__ A_log, const float* __restrict__ Dp,
    float* __restrict__ state_out)
{
    const int warp = threadIdx.x >> 5;
    const int lane = threadIdx.x & 31;
    const int wg = blockIdx.x * 8 + warp;   // 0..4095
    const int b = wg >> 11;                  // 0..1
    const int d = wg & (DINNER - 1);         // 0..2047

    const float a0 = -__expf(A_log[d * DSTATE + lane]);
    const float a1 = -__expf(A_log[d * DSTATE + lane + 32]);
    const float Dd = Dp[d];

    float s0 = 0.f, s1 = 0.f;
    for (int t = 0; t < LSEQ; ++t) {
        const int m = b * LSEQ + t;
        const float dtv = g_dt[(size_t)m * DINNER + d];
        const float xv  = g_xs[(size_t)m * DINNER + d];
        const float zv  = g_xz[(size_t)m * (2 * DINNER) + DINNER + d];
        const float b0 = g_Bm[m * DSTATE + lane];
        const float b1 = g_Bm[m * DSTATE + lane + 32];
        const float c0 = g_Cm[m * DSTATE + lane];
        const float c1 = g_Cm[m * DSTATE + lane + 32];

        const float dx = dtv * xv;
        s0 = __expf(dtv * a0) * s0 + dx * b0;
        s1 = __expf(dtv * a1) * s1 + dx * b1;

        float acc = s0 * c0 + s1 * c1;
#pragma unroll
        for (int o = 16; o; o >>= 1) acc += __shfl_xor_sync(0xffffffffu, acc, o);

        if (lane == 0) {
            float y = acc + Dd * xv;
            float sz = zv / (1.f + __expf(-zv));
            g_y[(size_t)m * DINNER + d] = y * sz;
        }
    }
    // final state: [B, d_inner, d_state]
    state_out[(size_t)(b * DINNER + d) * DSTATE + lane]      = s0;
    state_out[(size_t)(b * DINNER + d) * DSTATE + lane + 32] = s1;
}

// ---------------- launch ----------------
extern "C" void kernel_launch(void* const* d_in, const int* in_sizes, int n_in,
                              void* d_out, int out_size)
{
    const float* x          = (const float*)d_in[0];
    const float* in_proj_w  = (const float*)d_in[1];
    const float* conv_w     = (const float*)d_in[2];
    const float* conv_b     = (const float*)d_in[3];
    const float* x_proj_w   = (const float*)d_in[4];
    const float* dt_w       = (const float*)d_in[5];
    const float* dt_b       = (const float*)d_in[6];
    const float* A_log      = (const float*)d_in[7];
    const float* Dp         = (const float*)d_in[8];
    const float* out_proj_w = (const float*)d_in[9];
    float* out = (float*)d_out;

    void* p;
    cudaGetSymbolAddress(&p, g_xz);  float* p_xz = (float*)p;
    cudaGetSymbolAddress(&p, g_y);   float* p_y  = (float*)p;

    // 1) xz = x @ in_proj_w   (1024 x 1024 x 4096)
    sgemm128<<<dim3(2 * DINNER / 128, MROWS / 128), 256>>>(
        x, in_proj_w, p_xz, MROWS, 2 * DINNER, DMODEL);

    // 2) depthwise causal conv + SiLU
    conv_silu_kernel<<<MROWS, 256>>>(conv_w, conv_b);

    // 3) xp = xs @ x_proj_w (split-K) -> Bm, Cm, dt_raw
    xp_partial_kernel<<<dim3(MROWS / 16, KCH), 160>>>(x_proj_w);
    xp_reduce_kernel<<<MROWS, 160>>>();

    // 4) dt = softplus(dt_raw * dt_w + dt_b)
    dt_kernel<<<MROWS, 256>>>(dt_w, dt_b);

    // 5) selective scan -> g_y (gated) and new_state -> d_out tail
    scan_kernel<<<512, 256>>>(A_log, Dp, out + OUT_ELEMS);

    // 6) out = y @ out_proj_w  (1024 x 2048 x 1024)
    sgemm64<<<dim3(DMODEL / 64, MROWS / 64), 256>>>(
        p_y, out_proj_w, out, MROWS, DMODEL, DINNER);
}